// round 13
// baseline (speedup 1.0000x reference)
#include <cuda_runtime.h>
#include <math.h>

#define NPART 4096
#define NC 16

#define R_ON2  (1.7f * 1.7f)       /* 2.89  */
#define R_C2   (4.0f)              /* 2.0^2 */
#define CUT_INV_DENOM (1.0f / ((R_C2 - R_ON2) * (R_C2 - R_ON2) * (R_C2 - R_ON2)))
#define ALPHA_F 2.8f

#define NCELL_DIM 16
#define NCELLS (NCELL_DIM * NCELL_DIM * NCELL_DIM)   /* 4096 */
#define INV_CELLW 0.4f                               /* 1 / 2.5 */

#define SLOTS 8                                      /* direct-map width */
#define TPP 14                                       /* home + 13 forward cells */

#define NBLOCKS  148                                 /* one per SM, co-resident */
#define NTHREADS 256
#define GSTRIDE  (NBLOCKS * NTHREADS)                /* 37888 */

// scratch (no allocations; zero-initialized at load; all counters reset by
// the last block each launch -> graph replays see identical initial state)
__device__ float  g_wc[NPART * 32];   // per-particle 128B record: w[16] | ct[16]
__device__ float4 g_pos4[NPART];      // x,y,z,radius
__device__ int    g_cellid[NPART];    // cell | (mask << 12)
__device__ int    g_ccnt[NCELLS];     // per-cell member count
__device__ int    g_slots[NCELLS * SLOTS];  // (j<<1)|mask_j per member
__device__ int2   g_ovf[NPART];       // overflow (cell, (j<<1)|m); ~never used
__device__ unsigned int g_nov;        // overflow count
__device__ float  g_part[NBLOCKS];
__device__ unsigned int g_bar;        // grid barrier arrival counter
__device__ unsigned int g_count;      // completion counter

// 13 forward neighbor-cell offsets
__device__ __constant__ signed char FWD[13][3] = {
    { 1, 0, 0},
    {-1, 1, 0}, { 0, 1, 0}, { 1, 1, 0},
    {-1,-1, 1}, { 0,-1, 1}, { 1,-1, 1},
    {-1, 0, 1}, { 0, 0, 1}, { 1, 0, 1},
    {-1, 1, 1}, { 0, 1, 1}, { 1, 1, 1},
};

// ---------------------------------------------------------------------------
// Heavy path, symmetric unordered form: base_ij * (mi + mj). Each side's
// w|ct record is ONE aligned 128B line.
// ---------------------------------------------------------------------------
__device__ __forceinline__ float pair_sym(float r2, float ri, float rj,
                                          float mi, float mj,
                                          int ig, int jg) {
    const float4* __restrict__ ri4 = (const float4*)(g_wc + ig * 32);
    const float4* __restrict__ rj4 = (const float4*)(g_wc + jg * 32);
    float dot = 0.0f;
#pragma unroll
    for (int q = 0; q < 4; q++) {
        float4 wi = ri4[q], ci = ri4[q + 4];   // w: q0-3, ct: q4-7
        float4 wj = rj4[q], cj = rj4[q + 4];
        dot = fmaf(wi.x, cj.x, dot); dot = fmaf(wj.x, ci.x, dot);
        dot = fmaf(wi.y, cj.y, dot); dot = fmaf(wj.y, ci.y, dot);
        dot = fmaf(wi.z, cj.z, dot); dot = fmaf(wj.z, ci.z, dot);
        dot = fmaf(wi.w, cj.w, dot); dot = fmaf(wj.w, ci.w, dot);
    }
    float dr  = sqrtf(r2);
    float t   = R_C2 - r2;
    float poly = t * t * (R_C2 + 2.0f * r2 - 3.0f * R_ON2) * CUT_INV_DENOM;
    float cut  = (r2 < R_ON2) ? 1.0f : poly;
    float er  = 0.5f * dot;
    float eps = __fdividef(5.0f, 1.0f + __expf(-er)) + 0.3f;
    float u   = 1.0f - __expf(-ALPHA_F * (dr - (ri + rj)));
    return eps * (u * u - 1.0f) * cut * (mi + mj);
}

#define CE(a, b) { int lo = min(ids[a], ids[b]); int hi = max(ids[a], ids[b]); \
                   ids[a] = lo; ids[b] = hi; }

// ---------------------------------------------------------------------------
// Single fused persistent kernel: prep -> grid barrier -> energy -> reduce.
// 148 blocks x 256 (one per SM; all co-resident, so the software barrier is
// deadlock-free). Deterministic: fixed work maps, register-sorted neighbor
// order, fixed-order reductions; counters self-reset for graph replay.
// ---------------------------------------------------------------------------
__global__ __launch_bounds__(NTHREADS)
void fused_kernel(const float* __restrict__ pos,
                  const float* __restrict__ ct,
                  const float* __restrict__ E,
                  const float* __restrict__ rad,
                  float* __restrict__ out) {
    __shared__ float red[NTHREADS];
    __shared__ bool  is_last;

    const int tid  = threadIdx.x;
    const int gtid = blockIdx.x * NTHREADS + tid;

    // ---------------- Phase A: prep (grid-stride over 65536 units) --------
    for (int t = gtid; t < NPART * NC; t += GSTRIDE) {
        const int i = t >> 4;
        const int d = t & 15;

        const float4* __restrict__ ct4 = (const float4*)(ct + i * NC);
        float4 c0 = ct4[0], c1 = ct4[1], c2 = ct4[2], c3 = ct4[3];
        float sct[16] = {c0.x, c0.y, c0.z, c0.w, c1.x, c1.y, c1.z, c1.w,
                         c2.x, c2.y, c2.z, c2.w, c3.x, c3.y, c3.z, c3.w};

        const float4* __restrict__ Er4 = (const float4*)(E + i * 256 + d * NC);
        float4 r0 = Er4[0], r1 = Er4[1], r2 = Er4[2], r3 = Er4[3];
        float er[16] = {r0.x, r0.y, r0.z, r0.w, r1.x, r1.y, r1.z, r1.w,
                        r2.x, r2.y, r2.z, r2.w, r3.x, r3.y, r3.z, r3.w};

        const float* __restrict__ Ec = E + i * 256 + d;
        float w = 0.0f;
#pragma unroll
        for (int c = 0; c < 16; c++) {
            w = fmaf(sct[c], er[c] + __ldg(Ec + c * 16), w);
        }
        g_wc[i * 32 + d]      = 0.5f * w;
        g_wc[i * 32 + 16 + d] = sct[d];

        if (d == 0) {
            float s = 0.0f;
#pragma unroll
            for (int c = 0; c < 16; c++) s += sct[c];
            int m = (s > 0.0f) ? 1 : 0;
            float px = pos[3 * i], py = pos[3 * i + 1], pz = pos[3 * i + 2];
            g_pos4[i] = make_float4(px, py, pz, rad[i]);
            int cx = min((int)(px * INV_CELLW), NCELL_DIM - 1);
            int cy = min((int)(py * INV_CELLW), NCELL_DIM - 1);
            int cz = min((int)(pz * INV_CELLW), NCELL_DIM - 1);
            int cell = (cz << 8) | (cy << 4) | cx;
            g_cellid[i] = cell | (m << 12);
            int v = (i << 1) | m;
            int r = atomicAdd(&g_ccnt[cell], 1);
            if (r < SLOTS) {
                g_slots[cell * SLOTS + r] = v;
            } else {
                unsigned o = atomicAdd(&g_nov, 1u);
                g_ovf[o] = make_int2(cell, v);
            }
        }
    }

    // ---------------- software grid barrier (all blocks co-resident) ------
    __threadfence();
    __syncthreads();
    if (tid == 0) {
        atomicAdd(&g_bar, 1u);
        while (*((volatile unsigned int*)&g_bar) < NBLOCKS) { }
    }
    __syncthreads();
    __threadfence();

    // ---------------- Phase B: energy (grid-stride over 57344 units) ------
    float acc = 0.0f;

    for (int t = gtid; t < NPART * TPP; t += GSTRIDE) {
        const int i = t / TPP;
        const int r = t - i * TPP;

        const int    cid = g_cellid[i];
        const float4 pi  = g_pos4[i];
        const float  mi  = (float)((cid >> 12) & 1);

        int cx = cid & 15;
        int cy = (cid >> 4) & 15;
        int cz = (cid >> 8) & 15;
        if (r > 0) {
            cx += FWD[r - 1][0];
            cy += FWD[r - 1][1];
            cz += FWD[r - 1][2];
        }

        if (cx < 0 || cx >= NCELL_DIM || cy < 0 || cy >= NCELL_DIM ||
            cz < 0 || cz >= NCELL_DIM) continue;

        const int nc = (cz << 8) | (cy << 4) | cx;
        const int k  = g_ccnt[nc];
        const int4 s0 = ((const int4*)g_slots)[nc * 2];
        const int4 s1 = ((const int4*)g_slots)[nc * 2 + 1];

        if (k <= 0) continue;

        int ids[8] = {s0.x, s0.y, s0.z, s0.w, s1.x, s1.y, s1.z, s1.w};
#pragma unroll
        for (int u = 0; u < 8; u++)
            if (u >= k) ids[u] = 0x7fffffff;               // sentinel pad
        // Batcher odd-even 8-sort (19 compare-exchanges, registers only)
        CE(0,1) CE(2,3) CE(4,5) CE(6,7)
        CE(0,2) CE(1,3) CE(4,6) CE(5,7)
        CE(1,2) CE(5,6)
        CE(0,4) CE(1,5) CE(2,6) CE(3,7)
        CE(2,4) CE(3,5)
        CE(1,2) CE(3,4) CE(5,6)
#pragma unroll
        for (int u = 0; u < 8; u++) {
            int v = ids[u];
            int j = v >> 1;
            // home cell (r==0): j>i once-per-pair; forward cells: all j
            if (j < NPART && (r > 0 || j > i)) {
                float4 pj = g_pos4[j];
                float dx = pi.x - pj.x, dy = pi.y - pj.y, dz = pi.z - pj.z;
                float r2 = fmaf(dx, dx, fmaf(dy, dy, dz * dz));
                if (r2 < R_C2) {
                    float mj = (float)(v & 1);
                    acc += pair_sym(r2, pi.w, pj.w, mi, mj, i, j);
                }
            }
        }
        if (k > SLOTS) {
            // correct (never-expected) overflow path, ascending by id
            unsigned nov = g_nov;
            int last = -1;
            for (int m = 0; m < k - SLOTS; m++) {
                int bestv = 0x7fffffff;
                for (unsigned u = 0; u < nov; u++) {
                    int2 e = g_ovf[u];
                    if (e.x == nc && e.y > last && e.y < bestv) bestv = e.y;
                }
                if (bestv == 0x7fffffff) break;
                last = bestv;
                int j = bestv >> 1;
                if (!(r > 0 || j > i)) continue;
                float4 pj = g_pos4[j];
                float dx = pi.x - pj.x, dy = pi.y - pj.y, dz = pi.z - pj.z;
                float r2 = fmaf(dx, dx, fmaf(dy, dy, dz * dz));
                if (r2 < R_C2) {
                    float mj = (float)(bestv & 1);
                    acc += pair_sym(r2, pi.w, pj.w, mi, mj, i, j);
                }
            }
        }
    }

    // ---------------- deterministic block tree-reduce ----------------------
    red[tid] = acc;
    __syncthreads();
#pragma unroll
    for (int s = NTHREADS / 2; s > 0; s >>= 1) {
        if (tid < s) red[tid] += red[tid + s];
        __syncthreads();
    }

    if (tid == 0) {
        g_part[blockIdx.x] = red[0];
        __threadfence();
        unsigned int done = atomicAdd(&g_count, 1u);
        is_last = (done == NBLOCKS - 1);
    }
    __syncthreads();

    if (is_last) {
        // deterministic final reduction of 148 partials (fixed order)
        red[tid] = (tid < NBLOCKS) ? g_part[tid] : 0.0f;
        __syncthreads();
#pragma unroll
        for (int s = NTHREADS / 2; s > 0; s >>= 1) {
            if (tid < s) red[tid] += red[tid + s];
            __syncthreads();
        }
        if (tid == 0) {
            out[0] = 0.5f * red[0];
            g_count = 0;
            g_nov   = 0;
            g_bar   = 0;
        }
        // reset per-cell counts for the next graph replay
        for (int c = tid; c < NCELLS; c += NTHREADS) g_ccnt[c] = 0;
    }
}

// ---------------------------------------------------------------------------
// Launch. Inputs (metadata order): position (N*3), celltype (N*16),
// epsilon (N*256), radius (N). Output: scalar float.
// ---------------------------------------------------------------------------
extern "C" void kernel_launch(void* const* d_in, const int* in_sizes, int n_in,
                              void* d_out, int out_size) {
    const float* pos = (const float*)d_in[0];
    const float* ct  = (const float*)d_in[1];
    const float* E   = (const float*)d_in[2];
    const float* rad = (const float*)d_in[3];
    float* out = (float*)d_out;

    fused_kernel<<<NBLOCKS, NTHREADS>>>(pos, ct, E, rad, out);
}

// round 14
// speedup vs baseline: 1.2393x; 1.2393x over previous
#include <cuda_runtime.h>
#include <math.h>

#define NPART 4096
#define NC 16

#define R_ON2  (1.7f * 1.7f)       /* 2.89  */
#define R_C2   (4.0f)              /* 2.0^2 */
#define CUT_INV_DENOM (1.0f / ((R_C2 - R_ON2) * (R_C2 - R_ON2) * (R_C2 - R_ON2)))
#define ALPHA_F 2.8f

#define NCELL_DIM 16
#define NCELLS (NCELL_DIM * NCELL_DIM * NCELL_DIM)   /* 4096 */
#define INV_CELLW 0.4f                               /* 1 / 2.5 */

#define SLOTS 8                                      /* direct-map width */
#define TPP 14                                       /* home + 13 forward cells */

#define NBLOCKS  296                                 /* 2/SM; cap guarantees    */
#define NTHREADS 256                                 /* co-residency (<=444)    */
#define GSTRIDE  (NBLOCKS * NTHREADS)                /* 75776 >= both phases    */

// scratch (no allocations; zero-initialized at load; all counters reset by
// the last block each launch -> graph replays see identical initial state)
__device__ float  g_wc[NPART * 32];   // per-particle 128B record: w[16] | ct[16]
__device__ float4 g_pos4[NPART];      // x,y,z,radius
__device__ int    g_cellid[NPART];    // cell | (mask << 12)
__device__ int    g_ccnt[NCELLS];     // per-cell member count
__device__ int    g_slots[NCELLS * SLOTS];  // (j<<1)|mask_j per member
__device__ int2   g_ovf[NPART];       // overflow (cell, (j<<1)|m); ~never used
__device__ unsigned int g_nov;        // overflow count
__device__ float  g_part[NBLOCKS];
__device__ unsigned int g_bar;        // grid barrier arrival counter
__device__ unsigned int g_count;      // completion counter

// 13 forward neighbor-cell offsets
__device__ __constant__ signed char FWD[13][3] = {
    { 1, 0, 0},
    {-1, 1, 0}, { 0, 1, 0}, { 1, 1, 0},
    {-1,-1, 1}, { 0,-1, 1}, { 1,-1, 1},
    {-1, 0, 1}, { 0, 0, 1}, { 1, 0, 1},
    {-1, 1, 1}, { 0, 1, 1}, { 1, 1, 1},
};

// ---------------------------------------------------------------------------
// Heavy path, symmetric unordered form: base_ij * (mi + mj). Each side's
// w|ct record is ONE aligned 128B line.
// ---------------------------------------------------------------------------
__device__ __forceinline__ float pair_sym(float r2, float ri, float rj,
                                          float mi, float mj,
                                          int ig, int jg) {
    const float4* __restrict__ ri4 = (const float4*)(g_wc + ig * 32);
    const float4* __restrict__ rj4 = (const float4*)(g_wc + jg * 32);
    float dot = 0.0f;
#pragma unroll
    for (int q = 0; q < 4; q++) {
        float4 wi = ri4[q], ci = ri4[q + 4];   // w: q0-3, ct: q4-7
        float4 wj = rj4[q], cj = rj4[q + 4];
        dot = fmaf(wi.x, cj.x, dot); dot = fmaf(wj.x, ci.x, dot);
        dot = fmaf(wi.y, cj.y, dot); dot = fmaf(wj.y, ci.y, dot);
        dot = fmaf(wi.z, cj.z, dot); dot = fmaf(wj.z, ci.z, dot);
        dot = fmaf(wi.w, cj.w, dot); dot = fmaf(wj.w, ci.w, dot);
    }
    float dr  = sqrtf(r2);
    float t   = R_C2 - r2;
    float poly = t * t * (R_C2 + 2.0f * r2 - 3.0f * R_ON2) * CUT_INV_DENOM;
    float cut  = (r2 < R_ON2) ? 1.0f : poly;
    float er  = 0.5f * dot;
    float eps = __fdividef(5.0f, 1.0f + __expf(-er)) + 0.3f;
    float u   = 1.0f - __expf(-ALPHA_F * (dr - (ri + rj)));
    return eps * (u * u - 1.0f) * cut * (mi + mj);
}

#define CE(a, b) { int lo = min(ids[a], ids[b]); int hi = max(ids[a], ids[b]); \
                   ids[a] = lo; ids[b] = hi; }

// ---------------------------------------------------------------------------
// Single fused persistent kernel: prep -> grid barrier -> energy -> reduce.
// 296 blocks x 256. __launch_bounds__(256,3) caps regs at 85 -> HW capacity
// 444 blocks >= 296, so ALL blocks are co-resident regardless of placement:
// the software grid barrier cannot deadlock. Both phases complete in one
// grid-stride pass (full MLP). Deterministic: fixed work maps, register-
// sorted neighbor order, fixed-order reductions; counters self-reset.
// ---------------------------------------------------------------------------
__global__ __launch_bounds__(NTHREADS, 3)
void fused_kernel(const float* __restrict__ pos,
                  const float* __restrict__ ct,
                  const float* __restrict__ E,
                  const float* __restrict__ rad,
                  float* __restrict__ out) {
    __shared__ float red[NTHREADS];
    __shared__ bool  is_last;

    const int tid  = threadIdx.x;
    const int gtid = blockIdx.x * NTHREADS + tid;

    // ---------------- Phase A: prep (one pass; 65536 units) ---------------
    if (gtid < NPART * NC) {
        const int i = gtid >> 4;
        const int d = gtid & 15;

        const float4* __restrict__ ct4 = (const float4*)(ct + i * NC);
        float4 c0 = ct4[0], c1 = ct4[1], c2 = ct4[2], c3 = ct4[3];
        float sct[16] = {c0.x, c0.y, c0.z, c0.w, c1.x, c1.y, c1.z, c1.w,
                         c2.x, c2.y, c2.z, c2.w, c3.x, c3.y, c3.z, c3.w};

        const float4* __restrict__ Er4 = (const float4*)(E + i * 256 + d * NC);
        float4 r0 = Er4[0], r1 = Er4[1], r2 = Er4[2], r3 = Er4[3];
        float er[16] = {r0.x, r0.y, r0.z, r0.w, r1.x, r1.y, r1.z, r1.w,
                        r2.x, r2.y, r2.z, r2.w, r3.x, r3.y, r3.z, r3.w};

        const float* __restrict__ Ec = E + i * 256 + d;
        float w = 0.0f;
#pragma unroll
        for (int c = 0; c < 16; c++) {
            w = fmaf(sct[c], er[c] + __ldg(Ec + c * 16), w);
        }
        g_wc[i * 32 + d]      = 0.5f * w;
        g_wc[i * 32 + 16 + d] = sct[d];

        if (d == 0) {
            float s = 0.0f;
#pragma unroll
            for (int c = 0; c < 16; c++) s += sct[c];
            int m = (s > 0.0f) ? 1 : 0;
            float px = pos[3 * i], py = pos[3 * i + 1], pz = pos[3 * i + 2];
            g_pos4[i] = make_float4(px, py, pz, rad[i]);
            int cx = min((int)(px * INV_CELLW), NCELL_DIM - 1);
            int cy = min((int)(py * INV_CELLW), NCELL_DIM - 1);
            int cz = min((int)(pz * INV_CELLW), NCELL_DIM - 1);
            int cell = (cz << 8) | (cy << 4) | cx;
            g_cellid[i] = cell | (m << 12);
            int v = (i << 1) | m;
            int r = atomicAdd(&g_ccnt[cell], 1);
            if (r < SLOTS) {
                g_slots[cell * SLOTS + r] = v;
            } else {
                unsigned o = atomicAdd(&g_nov, 1u);
                g_ovf[o] = make_int2(cell, v);
            }
        }
    }

    // ---------------- software grid barrier (co-residency guaranteed) -----
    __threadfence();
    __syncthreads();
    if (tid == 0) {
        atomicAdd(&g_bar, 1u);
        while (*((volatile unsigned int*)&g_bar) < NBLOCKS) { }
    }
    __syncthreads();
    __threadfence();

    // ---------------- Phase B: energy (one pass; 57344 units) -------------
    float acc = 0.0f;

    if (gtid < NPART * TPP) {
        const int i = gtid / TPP;
        const int r = gtid - i * TPP;

        const int    cid = g_cellid[i];
        const float4 pi  = g_pos4[i];
        const float  mi  = (float)((cid >> 12) & 1);

        int cx = cid & 15;
        int cy = (cid >> 4) & 15;
        int cz = (cid >> 8) & 15;
        if (r > 0) {
            cx += FWD[r - 1][0];
            cy += FWD[r - 1][1];
            cz += FWD[r - 1][2];
        }

        if (cx >= 0 && cx < NCELL_DIM && cy >= 0 && cy < NCELL_DIM &&
            cz >= 0 && cz < NCELL_DIM) {
            const int nc = (cz << 8) | (cy << 4) | cx;
            const int k  = g_ccnt[nc];
            const int4 s0 = ((const int4*)g_slots)[nc * 2];
            const int4 s1 = ((const int4*)g_slots)[nc * 2 + 1];

            if (k > 0) {
                int ids[8] = {s0.x, s0.y, s0.z, s0.w, s1.x, s1.y, s1.z, s1.w};
#pragma unroll
                for (int u = 0; u < 8; u++)
                    if (u >= k) ids[u] = 0x7fffffff;       // sentinel pad
                // Batcher odd-even 8-sort (19 compare-exchanges, registers)
                CE(0,1) CE(2,3) CE(4,5) CE(6,7)
                CE(0,2) CE(1,3) CE(4,6) CE(5,7)
                CE(1,2) CE(5,6)
                CE(0,4) CE(1,5) CE(2,6) CE(3,7)
                CE(2,4) CE(3,5)
                CE(1,2) CE(3,4) CE(5,6)
#pragma unroll
                for (int u = 0; u < 8; u++) {
                    int v = ids[u];
                    int j = v >> 1;
                    // home cell (r==0): j>i once-per-pair; forward: all j
                    if (j < NPART && (r > 0 || j > i)) {
                        float4 pj = g_pos4[j];
                        float dx = pi.x - pj.x, dy = pi.y - pj.y,
                              dz = pi.z - pj.z;
                        float r2 = fmaf(dx, dx, fmaf(dy, dy, dz * dz));
                        if (r2 < R_C2) {
                            float mj = (float)(v & 1);
                            acc += pair_sym(r2, pi.w, pj.w, mi, mj, i, j);
                        }
                    }
                }
                if (k > SLOTS) {
                    // correct (never-expected) overflow path, ascending by id
                    unsigned nov = g_nov;
                    int last = -1;
                    for (int m = 0; m < k - SLOTS; m++) {
                        int bestv = 0x7fffffff;
                        for (unsigned u = 0; u < nov; u++) {
                            int2 e = g_ovf[u];
                            if (e.x == nc && e.y > last && e.y < bestv)
                                bestv = e.y;
                        }
                        if (bestv == 0x7fffffff) break;
                        last = bestv;
                        int j = bestv >> 1;
                        if (!(r > 0 || j > i)) continue;
                        float4 pj = g_pos4[j];
                        float dx = pi.x - pj.x, dy = pi.y - pj.y,
                              dz = pi.z - pj.z;
                        float r2 = fmaf(dx, dx, fmaf(dy, dy, dz * dz));
                        if (r2 < R_C2) {
                            float mj = (float)(bestv & 1);
                            acc += pair_sym(r2, pi.w, pj.w, mi, mj, i, j);
                        }
                    }
                }
            }
        }
    }

    // ---------------- deterministic block tree-reduce ----------------------
    red[tid] = acc;
    __syncthreads();
#pragma unroll
    for (int s = NTHREADS / 2; s > 0; s >>= 1) {
        if (tid < s) red[tid] += red[tid + s];
        __syncthreads();
    }

    if (tid == 0) {
        g_part[blockIdx.x] = red[0];
        __threadfence();
        unsigned int done = atomicAdd(&g_count, 1u);
        is_last = (done == NBLOCKS - 1);
    }
    __syncthreads();

    if (is_last) {
        // deterministic final reduction of 296 partials (fixed order)
        float v = (tid < NBLOCKS) ? g_part[tid] : 0.0f;
        if (tid + NTHREADS < NBLOCKS) v += g_part[tid + NTHREADS];
        red[tid] = v;
        __syncthreads();
#pragma unroll
        for (int s = NTHREADS / 2; s > 0; s >>= 1) {
            if (tid < s) red[tid] += red[tid + s];
            __syncthreads();
        }
        if (tid == 0) {
            out[0] = 0.5f * red[0];
            g_count = 0;
            g_nov   = 0;
            g_bar   = 0;
        }
        // reset per-cell counts for the next graph replay
        for (int c = tid; c < NCELLS; c += NTHREADS) g_ccnt[c] = 0;
    }
}

// ---------------------------------------------------------------------------
// Launch. Inputs (metadata order): position (N*3), celltype (N*16),
// epsilon (N*256), radius (N). Output: scalar float.
// ---------------------------------------------------------------------------
extern "C" void kernel_launch(void* const* d_in, const int* in_sizes, int n_in,
                              void* d_out, int out_size) {
    const float* pos = (const float*)d_in[0];
    const float* ct  = (const float*)d_in[1];
    const float* E   = (const float*)d_in[2];
    const float* rad = (const float*)d_in[3];
    float* out = (float*)d_out;

    fused_kernel<<<NBLOCKS, NTHREADS>>>(pos, ct, E, rad, out);
}

// round 15
// speedup vs baseline: 1.2557x; 1.0133x over previous
#include <cuda_runtime.h>
#include <math.h>

#define NPART 4096
#define NC 16

#define R_ON2  (1.7f * 1.7f)       /* 2.89  */
#define R_C2   (4.0f)              /* 2.0^2 */
#define CUT_INV_DENOM (1.0f / ((R_C2 - R_ON2) * (R_C2 - R_ON2) * (R_C2 - R_ON2)))
#define ALPHA_F 2.8f

#define NCELL_DIM 16
#define NCELLS (NCELL_DIM * NCELL_DIM * NCELL_DIM)   /* 4096 */
#define INV_CELLW 0.4f                               /* 1 / 2.5 */

#define SLOTS 8                                      /* direct-map width */
#define TPP 14                                       /* home + 13 forward cells */
#define EBLOCKS (NPART * TPP * 2 / 128)              /* 896 */

// scratch (no allocations; zero-initialized at load; counters reset by the
// last energy block -> graph replays see identical initial state)
__device__ float  g_wc[NPART * 32];   // per-particle 128B record: w[16] | ct[16]
__device__ float4 g_pos4[NPART];      // x,y,z,radius
__device__ int    g_cellid[NPART];    // cell | (mask << 12)
__device__ int    g_ccnt[NCELLS];     // per-cell member count
__device__ int    g_slots[NCELLS * SLOTS];  // (j<<1)|mask_j per member
__device__ int2   g_ovf[NPART];       // overflow (cell, (j<<1)|m); ~never used
__device__ unsigned int g_nov;        // overflow count
__device__ float  g_part[EBLOCKS];
__device__ unsigned int g_count;      // last-block counter

// 13 forward neighbor-cell offsets
__device__ __constant__ signed char FWD[13][3] = {
    { 1, 0, 0},
    {-1, 1, 0}, { 0, 1, 0}, { 1, 1, 0},
    {-1,-1, 1}, { 0,-1, 1}, { 1,-1, 1},
    {-1, 0, 1}, { 0, 0, 1}, { 1, 0, 1},
    {-1, 1, 1}, { 0, 1, 1}, { 1, 1, 1},
};

// ---------------------------------------------------------------------------
// Kernel 1: per-particle contraction w_i = ct_i^T E_sym_i, packed record,
// mask packing, cell binning. One thread per (particle, dim).
// ---------------------------------------------------------------------------
__global__ __launch_bounds__(128)
void prep_kernel(const float* __restrict__ pos,
                 const float* __restrict__ ct,
                 const float* __restrict__ E,
                 const float* __restrict__ rad) {
    const int t = blockIdx.x * 128 + threadIdx.x;   // 0 .. 65535
    const int i = t >> 4;
    const int d = t & 15;

    const float4* __restrict__ ct4 = (const float4*)(ct + i * NC);
    float4 c0 = ct4[0], c1 = ct4[1], c2 = ct4[2], c3 = ct4[3];
    float sct[16] = {c0.x, c0.y, c0.z, c0.w, c1.x, c1.y, c1.z, c1.w,
                     c2.x, c2.y, c2.z, c2.w, c3.x, c3.y, c3.z, c3.w};

    const float4* __restrict__ Er4 = (const float4*)(E + i * 256 + d * NC);
    float4 r0 = Er4[0], r1 = Er4[1], r2 = Er4[2], r3 = Er4[3];
    float er[16] = {r0.x, r0.y, r0.z, r0.w, r1.x, r1.y, r1.z, r1.w,
                    r2.x, r2.y, r2.z, r2.w, r3.x, r3.y, r3.z, r3.w};

    const float* __restrict__ Ec = E + i * 256 + d;
    float w = 0.0f;
#pragma unroll
    for (int c = 0; c < 16; c++) {
        w = fmaf(sct[c], er[c] + __ldg(Ec + c * 16), w);
    }
    g_wc[i * 32 + d]      = 0.5f * w;   // w half of the record
    g_wc[i * 32 + 16 + d] = sct[d];     // ct half of the record

    if (d == 0) {
        float s = 0.0f;
#pragma unroll
        for (int c = 0; c < 16; c++) s += sct[c];
        int m = (s > 0.0f) ? 1 : 0;
        float px = pos[3 * i], py = pos[3 * i + 1], pz = pos[3 * i + 2];
        g_pos4[i] = make_float4(px, py, pz, rad[i]);
        int cx = min((int)(px * INV_CELLW), NCELL_DIM - 1);
        int cy = min((int)(py * INV_CELLW), NCELL_DIM - 1);
        int cz = min((int)(pz * INV_CELLW), NCELL_DIM - 1);
        int cell = (cz << 8) | (cy << 4) | cx;
        g_cellid[i] = cell | (m << 12);
        int v = (i << 1) | m;
        int r = atomicAdd(&g_ccnt[cell], 1);
        if (r < SLOTS) {
            g_slots[cell * SLOTS + r] = v;
        } else {
            unsigned o = atomicAdd(&g_nov, 1u);
            g_ovf[o] = make_int2(cell, v);
        }
    }
}

// ---------------------------------------------------------------------------
// Heavy path, symmetric unordered form: base_ij * (mi + mj). Each side's
// w|ct record is ONE aligned 128B line.
// ---------------------------------------------------------------------------
__device__ __forceinline__ float pair_sym(float r2, float ri, float rj,
                                          float mi, float mj,
                                          int ig, int jg) {
    const float4* __restrict__ ri4 = (const float4*)(g_wc + ig * 32);
    const float4* __restrict__ rj4 = (const float4*)(g_wc + jg * 32);
    float dot = 0.0f;
#pragma unroll
    for (int q = 0; q < 4; q++) {
        float4 wi = ri4[q], ci = ri4[q + 4];   // w: q0-3, ct: q4-7
        float4 wj = rj4[q], cj = rj4[q + 4];
        dot = fmaf(wi.x, cj.x, dot); dot = fmaf(wj.x, ci.x, dot);
        dot = fmaf(wi.y, cj.y, dot); dot = fmaf(wj.y, ci.y, dot);
        dot = fmaf(wi.z, cj.z, dot); dot = fmaf(wj.z, ci.z, dot);
        dot = fmaf(wi.w, cj.w, dot); dot = fmaf(wj.w, ci.w, dot);
    }
    float dr  = sqrtf(r2);
    float t   = R_C2 - r2;
    float poly = t * t * (R_C2 + 2.0f * r2 - 3.0f * R_ON2) * CUT_INV_DENOM;
    float cut  = (r2 < R_ON2) ? 1.0f : poly;
    float er  = 0.5f * dot;
    float eps = __fdividef(5.0f, 1.0f + __expf(-er)) + 0.3f;
    float u   = 1.0f - __expf(-ALPHA_F * (dr - (ri + rj)));
    return eps * (u * u - 1.0f) * cut * (mi + mj);
}

#define CE(a, b) { int lo = min(ids[a], ids[b]); int hi = max(ids[a], ids[b]); \
                   ids[a] = lo; ids[b] = hi; }

// ---------------------------------------------------------------------------
// Kernel 2: energy. TWO threads per (particle, {home + 13 forward cells}):
// both do the cheap cell-load + Batcher sort (broadcast/ALU, ~free), then
// split the expensive pair evaluations by sorted-rank parity (half 0 takes
// ranks 0,2,4,6; half 1 takes 1,3,5,7). Sorted order is input-determined,
// so ownership is fixed -> bitwise deterministic. 896 blocks x 128; thread
// count 114688 doubles the occupancy ceiling vs one-thread-per-cell.
// ---------------------------------------------------------------------------
__global__ __launch_bounds__(128, 6)
void energy_kernel(float* __restrict__ out) {
    __shared__ float red[128];
    __shared__ bool  is_last;

    const int t    = blockIdx.x * 128 + threadIdx.x;  // 0 .. 114687
    const int tid  = threadIdx.x;
    const int i    = t / (TPP * 2);
    const int rr   = t - i * (TPP * 2);
    const int r    = rr >> 1;       // cell index 0..13
    const int half = rr & 1;        // sorted-rank parity this thread owns

    const int    cid = g_cellid[i];   // parallel loads
    const float4 pi  = g_pos4[i];
    const float  mi  = (float)((cid >> 12) & 1);

    int cx = cid & 15;
    int cy = (cid >> 4) & 15;
    int cz = (cid >> 8) & 15;
    if (r > 0) {
        cx += FWD[r - 1][0];
        cy += FWD[r - 1][1];
        cz += FWD[r - 1][2];
    }

    float acc = 0.0f;

    if (cx >= 0 && cx < NCELL_DIM && cy >= 0 && cy < NCELL_DIM &&
        cz >= 0 && cz < NCELL_DIM) {
        const int nc = (cz << 8) | (cy << 4) | cx;
        const int k  = __ldg(&g_ccnt[nc]);                 // LDG
        const int4 s0 = __ldg(&((const int4*)g_slots)[nc * 2]);  // parallel
        const int4 s1 = __ldg(&((const int4*)g_slots)[nc * 2 + 1]);

        if (k > 0) {
            int ids[8] = {s0.x, s0.y, s0.z, s0.w, s1.x, s1.y, s1.z, s1.w};
#pragma unroll
            for (int u = 0; u < 8; u++)
                if (u >= k) ids[u] = 0x7fffffff;           // sentinel pad
            // Batcher odd-even 8-sort (19 compare-exchanges, registers only)
            CE(0,1) CE(2,3) CE(4,5) CE(6,7)
            CE(0,2) CE(1,3) CE(4,6) CE(5,7)
            CE(1,2) CE(5,6)
            CE(0,4) CE(1,5) CE(2,6) CE(3,7)
            CE(2,4) CE(3,5)
            CE(1,2) CE(3,4) CE(5,6)
#pragma unroll
            for (int u = 0; u < 8; u++) {
                if ((u & 1) != half) continue;             // rank-parity split
                int v = ids[u];
                int j = v >> 1;
                // home cell (r==0): j>i once-per-pair; forward cells: all j
                if (j < NPART && (r > 0 || j > i)) {
                    float4 pj = g_pos4[j];
                    float dx = pi.x - pj.x, dy = pi.y - pj.y, dz = pi.z - pj.z;
                    float r2 = fmaf(dx, dx, fmaf(dy, dy, dz * dz));
                    if (r2 < R_C2) {
                        float mj = (float)(v & 1);
                        acc += pair_sym(r2, pi.w, pj.w, mi, mj, i, j);
                    }
                }
            }
            if (k > SLOTS) {
                // correct (never-expected) overflow path, ascending by id;
                // split across the two threads by index parity
                unsigned nov = g_nov;
                int last = -1;
                for (int m = 0; m < k - SLOTS; m++) {
                    int bestv = 0x7fffffff;
                    for (unsigned u = 0; u < nov; u++) {
                        int2 e = g_ovf[u];
                        if (e.x == nc && e.y > last && e.y < bestv) bestv = e.y;
                    }
                    if (bestv == 0x7fffffff) break;
                    last = bestv;
                    if ((m & 1) != half) continue;
                    int j = bestv >> 1;
                    if (!(r > 0 || j > i)) continue;
                    float4 pj = g_pos4[j];
                    float dx = pi.x - pj.x, dy = pi.y - pj.y, dz = pi.z - pj.z;
                    float r2 = fmaf(dx, dx, fmaf(dy, dy, dz * dz));
                    if (r2 < R_C2) {
                        float mj = (float)(bestv & 1);
                        acc += pair_sym(r2, pi.w, pj.w, mi, mj, i, j);
                    }
                }
            }
        }
    }

    // deterministic block tree-reduce (128 threads)
    red[tid] = acc;
    __syncthreads();
#pragma unroll
    for (int s = 64; s > 0; s >>= 1) {
        if (tid < s) red[tid] += red[tid + s];
        __syncthreads();
    }

    if (tid == 0) {
        g_part[blockIdx.x] = red[0];
        __threadfence();
        unsigned int done = atomicAdd(&g_count, 1u);
        is_last = (done == EBLOCKS - 1);
    }
    __syncthreads();

    if (is_last) {
        // deterministic final reduction of 896 partials (fixed order)
        float v = 0.0f;
#pragma unroll
        for (int q = 0; q < 7; q++) {
            int idx = tid + q * 128;
            if (idx < EBLOCKS) v += g_part[idx];
        }
        red[tid] = v;
        __syncthreads();
#pragma unroll
        for (int s = 64; s > 0; s >>= 1) {
            if (tid < s) red[tid] += red[tid + s];
            __syncthreads();
        }
        if (tid == 0) {
            out[0] = 0.5f * red[0];
            g_count = 0;
            g_nov   = 0;
        }
        // reset per-cell counts for the next graph replay
        for (int c = tid; c < NCELLS; c += 128) g_ccnt[c] = 0;
    }
}

// ---------------------------------------------------------------------------
// Launch. Inputs (metadata order): position (N*3), celltype (N*16),
// epsilon (N*256), radius (N). Output: scalar float.
// ---------------------------------------------------------------------------
extern "C" void kernel_launch(void* const* d_in, const int* in_sizes, int n_in,
                              void* d_out, int out_size) {
    const float* pos = (const float*)d_in[0];
    const float* ct  = (const float*)d_in[1];
    const float* E   = (const float*)d_in[2];
    const float* rad = (const float*)d_in[3];
    float* out = (float*)d_out;

    prep_kernel<<<NPART * NC / 128, 128>>>(pos, ct, E, rad);
    energy_kernel<<<EBLOCKS, 128>>>(out);
}

// round 16
// speedup vs baseline: 1.4289x; 1.1379x over previous
#include <cuda_runtime.h>
#include <math.h>

#define NPART 4096
#define NC 16

#define R_ON2  (1.7f * 1.7f)       /* 2.89  */
#define R_C2   (4.0f)              /* 2.0^2 */
#define CUT_INV_DENOM (1.0f / ((R_C2 - R_ON2) * (R_C2 - R_ON2) * (R_C2 - R_ON2)))
#define ALPHA_F 2.8f

#define NCELL_DIM 16
#define NCELLS (NCELL_DIM * NCELL_DIM * NCELL_DIM)   /* 4096 */
#define INV_CELLW 0.4f                               /* 1 / 2.5 */

#define SLOTS 8                                      /* direct-map width */
#define TPP 14                                       /* home + 13 forward cells */
#define EBLOCKS (NPART * TPP / 128)                  /* 448 */

// scratch (no allocations; zero-initialized at load; counters reset by the
// last energy block -> graph replays see identical initial state)
__device__ float  g_wc[NPART * 32];   // per-particle 128B record: w[16] | ct[16]
__device__ float4 g_pos4[NPART];      // x,y,z,radius
__device__ int    g_cellid[NPART];    // cell | (mask << 12)
__device__ int    g_ccnt[NCELLS];     // per-cell member count
__device__ int    g_slots[NCELLS * SLOTS];  // (j<<1)|mask_j per member
__device__ int2   g_ovf[NPART];       // overflow (cell, (j<<1)|m); ~never used
__device__ unsigned int g_nov;        // overflow count
__device__ float  g_part[EBLOCKS];
__device__ unsigned int g_count;      // last-block counter

// 13 forward neighbor-cell offsets
__device__ __constant__ signed char FWD[13][3] = {
    { 1, 0, 0},
    {-1, 1, 0}, { 0, 1, 0}, { 1, 1, 0},
    {-1,-1, 1}, { 0,-1, 1}, { 1,-1, 1},
    {-1, 0, 1}, { 0, 0, 1}, { 1, 0, 1},
    {-1, 1, 1}, { 0, 1, 1}, { 1, 1, 1},
};

// ---------------------------------------------------------------------------
// Kernel 1: per-particle contraction w_i = ct_i^T E_sym_i, packed record,
// mask packing, cell binning. TWO threads per (particle, dim): each handles
// half of the c-sum (2x threads in flight vs R12; same total loads), halves
// combined via shfl_xor. All indexing is pointer arithmetic (no runtime-
// indexed register arrays -> no local-memory spills).
// ---------------------------------------------------------------------------
__global__ __launch_bounds__(128)
void prep_kernel(const float* __restrict__ pos,
                 const float* __restrict__ ct,
                 const float* __restrict__ E,
                 const float* __restrict__ rad) {
    const int t    = blockIdx.x * 128 + threadIdx.x;   // 0 .. 131071
    const int i    = t >> 5;        // particle
    const int rr   = t & 31;
    const int d    = rr >> 1;       // output dim 0..15
    const int half = rr & 1;        // c-range half

    // half of celltype (2 x LDG.128, pointer-indexed)
    const float4* __restrict__ ctp = (const float4*)(ct + i * NC) + half * 2;
    float4 cA = ctp[0], cB = ctp[1];

    // half of row d (2 x LDG.128)
    const float4* __restrict__ rp = (const float4*)(E + i * 256 + d * NC) + half * 2;
    float4 rA = rp[0], rB = rp[1];

    // half of column d (8 scalar LDG, 64B-contiguous across the d-lanes)
    const float* __restrict__ Ec = E + i * 256 + d + half * 8 * NC;

    float w;
    w  = cA.x * (rA.x + __ldg(Ec + 0 * NC));
    w  = fmaf(cA.y, rA.y + __ldg(Ec + 1 * NC), w);
    w  = fmaf(cA.z, rA.z + __ldg(Ec + 2 * NC), w);
    w  = fmaf(cA.w, rA.w + __ldg(Ec + 3 * NC), w);
    w  = fmaf(cB.x, rB.x + __ldg(Ec + 4 * NC), w);
    w  = fmaf(cB.y, rB.y + __ldg(Ec + 5 * NC), w);
    w  = fmaf(cB.z, rB.z + __ldg(Ec + 6 * NC), w);
    w  = fmaf(cB.w, rB.w + __ldg(Ec + 7 * NC), w);

    w += __shfl_xor_sync(0xffffffffu, w, 1);   // combine the two halves

    if (half == 0) {
        g_wc[i * 32 + d]      = 0.5f * w;
        g_wc[i * 32 + 16 + d] = __ldg(ct + i * NC + d);
    }

    if (rr == 0) {   // one thread per particle: mask, pos4, binning
        const float4* __restrict__ c4 = (const float4*)(ct + i * NC);
        float4 q0 = c4[0], q1 = c4[1], q2 = c4[2], q3 = c4[3];
        float s = (q0.x + q0.y + q0.z + q0.w) + (q1.x + q1.y + q1.z + q1.w)
                + (q2.x + q2.y + q2.z + q2.w) + (q3.x + q3.y + q3.z + q3.w);
        int m = (s > 0.0f) ? 1 : 0;
        float px = pos[3 * i], py = pos[3 * i + 1], pz = pos[3 * i + 2];
        g_pos4[i] = make_float4(px, py, pz, rad[i]);
        int cx = min((int)(px * INV_CELLW), NCELL_DIM - 1);
        int cy = min((int)(py * INV_CELLW), NCELL_DIM - 1);
        int cz = min((int)(pz * INV_CELLW), NCELL_DIM - 1);
        int cell = (cz << 8) | (cy << 4) | cx;
        g_cellid[i] = cell | (m << 12);
        int v = (i << 1) | m;
        int r = atomicAdd(&g_ccnt[cell], 1);
        if (r < SLOTS) {
            g_slots[cell * SLOTS + r] = v;
        } else {
            unsigned o = atomicAdd(&g_nov, 1u);
            g_ovf[o] = make_int2(cell, v);
        }
    }
}

// ---------------------------------------------------------------------------
// Heavy path, symmetric unordered form: base_ij * (mi + mj). Each side's
// w|ct record is ONE aligned 128B line.
// ---------------------------------------------------------------------------
__device__ __forceinline__ float pair_sym(float r2, float ri, float rj,
                                          float mi, float mj,
                                          int ig, int jg) {
    const float4* __restrict__ ri4 = (const float4*)(g_wc + ig * 32);
    const float4* __restrict__ rj4 = (const float4*)(g_wc + jg * 32);
    float dot = 0.0f;
#pragma unroll
    for (int q = 0; q < 4; q++) {
        float4 wi = ri4[q], ci = ri4[q + 4];   // w: q0-3, ct: q4-7
        float4 wj = rj4[q], cj = rj4[q + 4];
        dot = fmaf(wi.x, cj.x, dot); dot = fmaf(wj.x, ci.x, dot);
        dot = fmaf(wi.y, cj.y, dot); dot = fmaf(wj.y, ci.y, dot);
        dot = fmaf(wi.z, cj.z, dot); dot = fmaf(wj.z, ci.z, dot);
        dot = fmaf(wi.w, cj.w, dot); dot = fmaf(wj.w, ci.w, dot);
    }
    float dr  = sqrtf(r2);
    float t   = R_C2 - r2;
    float poly = t * t * (R_C2 + 2.0f * r2 - 3.0f * R_ON2) * CUT_INV_DENOM;
    float cut  = (r2 < R_ON2) ? 1.0f : poly;
    float er  = 0.5f * dot;
    float eps = __fdividef(5.0f, 1.0f + __expf(-er)) + 0.3f;
    float u   = 1.0f - __expf(-ALPHA_F * (dr - (ri + rj)));
    return eps * (u * u - 1.0f) * cut * (mi + mj);
}

#define CE(a, b) { int lo = min(ids[a], ids[b]); int hi = max(ids[a], ids[b]); \
                   ids[a] = lo; ids[b] = hi; }

// ---------------------------------------------------------------------------
// Kernel 2: energy (byte-identical to the 14.8us R12 version). One thread
// per (particle, {home + 13 forward cells}). Home cell uses j > i; forward
// cells own each cross-cell pair uniquely. 448 blocks x 128. Slot values
// (j<<1)|m sorted ascending by a Batcher-8 register network (determinism).
// Fused final reduction + counter reset for graph replay.
// ---------------------------------------------------------------------------
__global__ __launch_bounds__(128, 6)
void energy_kernel(float* __restrict__ out) {
    __shared__ float red[128];
    __shared__ bool  is_last;

    const int t   = blockIdx.x * 128 + threadIdx.x;  // 0 .. 57343
    const int tid = threadIdx.x;
    const int i   = t / TPP;
    const int r   = t - i * TPP;

    const int    cid = g_cellid[i];   // parallel loads
    const float4 pi  = g_pos4[i];
    const float  mi  = (float)((cid >> 12) & 1);

    int cx = cid & 15;
    int cy = (cid >> 4) & 15;
    int cz = (cid >> 8) & 15;
    if (r > 0) {
        cx += FWD[r - 1][0];
        cy += FWD[r - 1][1];
        cz += FWD[r - 1][2];
    }

    float acc = 0.0f;

    if (cx >= 0 && cx < NCELL_DIM && cy >= 0 && cy < NCELL_DIM &&
        cz >= 0 && cz < NCELL_DIM) {
        const int nc = (cz << 8) | (cy << 4) | cx;
        const int k  = g_ccnt[nc];                         // LDG
        const int4 s0 = ((const int4*)g_slots)[nc * 2];    // LDG.128 (parallel)
        const int4 s1 = ((const int4*)g_slots)[nc * 2 + 1];

        if (k > 0) {
            int ids[8] = {s0.x, s0.y, s0.z, s0.w, s1.x, s1.y, s1.z, s1.w};
#pragma unroll
            for (int u = 0; u < 8; u++)
                if (u >= k) ids[u] = 0x7fffffff;           // sentinel pad
            // Batcher odd-even 8-sort (19 compare-exchanges, registers only)
            CE(0,1) CE(2,3) CE(4,5) CE(6,7)
            CE(0,2) CE(1,3) CE(4,6) CE(5,7)
            CE(1,2) CE(5,6)
            CE(0,4) CE(1,5) CE(2,6) CE(3,7)
            CE(2,4) CE(3,5)
            CE(1,2) CE(3,4) CE(5,6)
#pragma unroll
            for (int u = 0; u < 8; u++) {
                int v = ids[u];
                int j = v >> 1;
                // home cell (r==0): j>i once-per-pair; forward cells: all j
                if (j < NPART && (r > 0 || j > i)) {
                    float4 pj = g_pos4[j];
                    float dx = pi.x - pj.x, dy = pi.y - pj.y, dz = pi.z - pj.z;
                    float r2 = fmaf(dx, dx, fmaf(dy, dy, dz * dz));
                    if (r2 < R_C2) {
                        float mj = (float)(v & 1);
                        acc += pair_sym(r2, pi.w, pj.w, mi, mj, i, j);
                    }
                }
            }
            if (k > SLOTS) {
                // correct (never-expected) overflow path, ascending by id
                unsigned nov = g_nov;
                int last = -1;
                for (int m = 0; m < k - SLOTS; m++) {
                    int bestv = 0x7fffffff;
                    for (unsigned u = 0; u < nov; u++) {
                        int2 e = g_ovf[u];
                        if (e.x == nc && e.y > last && e.y < bestv) bestv = e.y;
                    }
                    if (bestv == 0x7fffffff) break;
                    last = bestv;
                    int j = bestv >> 1;
                    if (!(r > 0 || j > i)) continue;
                    float4 pj = g_pos4[j];
                    float dx = pi.x - pj.x, dy = pi.y - pj.y, dz = pi.z - pj.z;
                    float r2 = fmaf(dx, dx, fmaf(dy, dy, dz * dz));
                    if (r2 < R_C2) {
                        float mj = (float)(bestv & 1);
                        acc += pair_sym(r2, pi.w, pj.w, mi, mj, i, j);
                    }
                }
            }
        }
    }

    // deterministic block tree-reduce (128 threads)
    red[tid] = acc;
    __syncthreads();
#pragma unroll
    for (int s = 64; s > 0; s >>= 1) {
        if (tid < s) red[tid] += red[tid + s];
        __syncthreads();
    }

    if (tid == 0) {
        g_part[blockIdx.x] = red[0];
        __threadfence();
        unsigned int done = atomicAdd(&g_count, 1u);
        is_last = (done == EBLOCKS - 1);
    }
    __syncthreads();

    if (is_last) {
        // deterministic final reduction of 448 partials (fixed order)
        float v = 0.0f;
#pragma unroll
        for (int q = 0; q < 4; q++) {
            int idx = tid + q * 128;
            if (idx < EBLOCKS) v += g_part[idx];
        }
        red[tid] = v;
        __syncthreads();
#pragma unroll
        for (int s = 64; s > 0; s >>= 1) {
            if (tid < s) red[tid] += red[tid + s];
            __syncthreads();
        }
        if (tid == 0) {
            out[0] = 0.5f * red[0];
            g_count = 0;
            g_nov   = 0;
        }
        // reset per-cell counts for the next graph replay
        for (int c = tid; c < NCELLS; c += 128) g_ccnt[c] = 0;
    }
}

// ---------------------------------------------------------------------------
// Launch. Inputs (metadata order): position (N*3), celltype (N*16),
// epsilon (N*256), radius (N). Output: scalar float.
// ---------------------------------------------------------------------------
extern "C" void kernel_launch(void* const* d_in, const int* in_sizes, int n_in,
                              void* d_out, int out_size) {
    const float* pos = (const float*)d_in[0];
    const float* ct  = (const float*)d_in[1];
    const float* E   = (const float*)d_in[2];
    const float* rad = (const float*)d_in[3];
    float* out = (float*)d_out;

    prep_kernel<<<NPART * 32 / 128, 128>>>(pos, ct, E, rad);
    energy_kernel<<<EBLOCKS, 128>>>(out);
}